// round 1
// baseline (speedup 1.0000x reference)
#include <cuda_runtime.h>

#define Nn   8192
#define FIN  512
#define NHID 128
#define NCLS 64
#define CPRE 16

// ---------------- scratch (static device globals; no allocation) ----------------
__device__ float    g_Wh1[Nn][2 * NHID];   // layer-1 Wh, both heads concat (8 MB)
__device__ float    g_f1h[2][Nn];
__device__ float    g_f2h[2][Nn];
__device__ unsigned g_max1[2];
__device__ float    g_h[Nn][2 * NHID];     // layer-1 output (8 MB)
__device__ float    g_Wh2[Nn][NCLS];       // 2 MB
__device__ float    g_f1b[Nn];
__device__ float    g_f2b[Nn];
__device__ unsigned g_max2;
__device__ float    g_mu[Nn][NCLS];        // 2 MB

// monotone float<->uint encoding for atomicMax on floats
__device__ __forceinline__ unsigned enc_f(float f) {
    unsigned u = __float_as_uint(f);
    return (u & 0x80000000u) ? ~u : (u | 0x80000000u);
}
__device__ __forceinline__ float dec_f(unsigned u) {
    return __uint_as_float((u & 0x80000000u) ? (u & 0x7fffffffu) : ~u);
}
__device__ __forceinline__ float lrelu(float x) { return x >= 0.f ? x : 0.2f * x; }
__device__ __forceinline__ float eluf(float x)  { return x > 0.f ? x : expm1f(x); }

__global__ void k_init() {
    g_max1[0] = 0u; g_max1[1] = 0u; g_max2 = 0u;
}

// ---------------- K1: Wh = x @ W  (both heads, output cols = h*128+c) ----------------
__global__ void __launch_bounds__(256) k_gemm1(const float* __restrict__ x,
                                               const float* __restrict__ W) {
    __shared__ float xs[16][64];   // [k][i]
    __shared__ float ws[16][64];   // [k][c]
    int i0 = blockIdx.x * 64;
    int c0 = blockIdx.y * 64;
    const float* Wp = W + (size_t)(c0 >> 7) * FIN * NHID;  // head base
    int cW = c0 & (NHID - 1);
    int tid = threadIdx.x;
    int tx = tid & 15, ty = tid >> 4;
    float acc[4][4] = {};
    for (int k0 = 0; k0 < FIN; k0 += 16) {
        {
            int r = tid >> 2, kk = (tid & 3) * 4;
            float4 v = *(const float4*)&x[(size_t)(i0 + r) * FIN + k0 + kk];
            xs[kk + 0][r] = v.x; xs[kk + 1][r] = v.y;
            xs[kk + 2][r] = v.z; xs[kk + 3][r] = v.w;
            int rk = tid >> 4, cc = (tid & 15) * 4;
            *(float4*)&ws[rk][cc] = *(const float4*)&Wp[(size_t)(k0 + rk) * NHID + cW + cc];
        }
        __syncthreads();
#pragma unroll
        for (int kk = 0; kk < 16; kk++) {
            float4 a = *(float4*)&xs[kk][ty * 4];
            float4 b = *(float4*)&ws[kk][tx * 4];
            float av[4] = {a.x, a.y, a.z, a.w};
            float bv[4] = {b.x, b.y, b.z, b.w};
#pragma unroll
            for (int i = 0; i < 4; i++)
#pragma unroll
                for (int j = 0; j < 4; j++)
                    acc[i][j] += av[i] * bv[j];
        }
        __syncthreads();
    }
#pragma unroll
    for (int i = 0; i < 4; i++) {
        float4 o = make_float4(acc[i][0], acc[i][1], acc[i][2], acc[i][3]);
        *(float4*)&g_Wh1[i0 + ty * 4 + i][c0 + tx * 4] = o;
    }
}

// ---------------- K2: per-row f1,f2 for both heads + global max(f2) ----------------
__global__ void __launch_bounds__(256) k_fheads(const float* __restrict__ a_heads) {
    int tid = threadIdx.x;
    int w = tid >> 5, lane = tid & 31;
    int row = blockIdx.x * 8 + w;
    float4 w0 = *(const float4*)&g_Wh1[row][lane * 4];
    float4 w1 = *(const float4*)&g_Wh1[row][NHID + lane * 4];
    float4 a0s = *(const float4*)&a_heads[lane * 4];
    float4 a0t = *(const float4*)&a_heads[NHID + lane * 4];
    float4 a1s = *(const float4*)&a_heads[2 * NHID + lane * 4];
    float4 a1t = *(const float4*)&a_heads[3 * NHID + lane * 4];
    float f10 = w0.x * a0s.x + w0.y * a0s.y + w0.z * a0s.z + w0.w * a0s.w;
    float f20 = w0.x * a0t.x + w0.y * a0t.y + w0.z * a0t.z + w0.w * a0t.w;
    float f11 = w1.x * a1s.x + w1.y * a1s.y + w1.z * a1s.z + w1.w * a1s.w;
    float f21 = w1.x * a1t.x + w1.y * a1t.y + w1.z * a1t.z + w1.w * a1t.w;
#pragma unroll
    for (int off = 16; off; off >>= 1) {
        f10 += __shfl_xor_sync(0xffffffffu, f10, off);
        f20 += __shfl_xor_sync(0xffffffffu, f20, off);
        f11 += __shfl_xor_sync(0xffffffffu, f11, off);
        f21 += __shfl_xor_sync(0xffffffffu, f21, off);
    }
    __shared__ float s0[8], s1[8];
    if (lane == 0) {
        g_f1h[0][row] = f10; g_f2h[0][row] = f20;
        g_f1h[1][row] = f11; g_f2h[1][row] = f21;
        s0[w] = f20; s1[w] = f21;
    }
    __syncthreads();
    if (tid == 0) {
        float m0 = s0[0], m1 = s1[0];
#pragma unroll
        for (int k = 1; k < 8; k++) { m0 = fmaxf(m0, s0[k]); m1 = fmaxf(m1, s1[k]); }
        atomicMax(&g_max1[0], enc_f(m0));
        atomicMax(&g_max1[1], enc_f(m1));
    }
}

// ---------------- K4: layer-1 fused masked attention, both heads ----------------
// 32 rows/CTA, 8 warps x 4 rows; streams j in tiles of 32; fixed-scale softmax.
__global__ void __launch_bounds__(256, 2) k_attn1(const int* __restrict__ adj) {
    __shared__ float whS[32][256];   // 32 KB
    __shared__ int   adjS[32][32];   // 4 KB
    __shared__ float f2S[2][32];
    int tid = threadIdx.x;
    int w = tid >> 5, lane = tid & 31;
    int i0 = blockIdx.x * 32;
    float F0 = dec_f(g_max1[0]), F1 = dec_f(g_max1[1]);
    float f10[4], f11[4], mh0[4], mh1[4];
#pragma unroll
    for (int rr = 0; rr < 4; rr++) {
        int i = i0 + w * 4 + rr;
        f10[rr] = g_f1h[0][i]; f11[rr] = g_f1h[1][i];
        mh0[rr] = lrelu(f10[rr] + F0);
        mh1[rr] = lrelu(f11[rr] + F1);
    }
    float4 acc0[4], acc1[4];
    float ls0[4], ls1[4];
#pragma unroll
    for (int rr = 0; rr < 4; rr++) {
        acc0[rr] = make_float4(0.f, 0.f, 0.f, 0.f);
        acc1[rr] = make_float4(0.f, 0.f, 0.f, 0.f);
        ls0[rr] = 0.f; ls1[rr] = 0.f;
    }

    for (int j0 = 0; j0 < Nn; j0 += 32) {
        __syncthreads();
        {
            const float4* src = (const float4*)&g_Wh1[j0][0];
            float4* dst = (float4*)&whS[0][0];
#pragma unroll
            for (int t = 0; t < 8; t++) dst[tid + t * 256] = src[tid + t * 256];
            int r = tid >> 3, c = (tid & 7) * 4;
            *(int4*)&adjS[r][c] = *(const int4*)&adj[(size_t)(i0 + r) * Nn + j0 + c];
            if (tid < 32) { f2S[0][tid] = g_f2h[0][j0 + tid]; f2S[1][tid] = g_f2h[1][j0 + tid]; }
        }
        __syncthreads();
        float p0[4], p1[4];
#pragma unroll
        for (int rr = 0; rr < 4; rr++) {
            int m = adjS[w * 4 + rr][lane];
            float s0 = lrelu(f10[rr] + f2S[0][lane]);
            float s1 = lrelu(f11[rr] + f2S[1][lane]);
            p0[rr] = m ? __expf(s0 - mh0[rr]) : 0.f;
            p1[rr] = m ? __expf(s1 - mh1[rr]) : 0.f;
            ls0[rr] += p0[rr]; ls1[rr] += p1[rr];
        }
#pragma unroll 8
        for (int jj = 0; jj < 32; jj++) {
            float4 w0 = *(float4*)&whS[jj][lane * 4];
            float4 w1 = *(float4*)&whS[jj][NHID + lane * 4];
#pragma unroll
            for (int rr = 0; rr < 4; rr++) {
                float pj0 = __shfl_sync(0xffffffffu, p0[rr], jj);
                float pj1 = __shfl_sync(0xffffffffu, p1[rr], jj);
                acc0[rr].x += pj0 * w0.x; acc0[rr].y += pj0 * w0.y;
                acc0[rr].z += pj0 * w0.z; acc0[rr].w += pj0 * w0.w;
                acc1[rr].x += pj1 * w1.x; acc1[rr].y += pj1 * w1.y;
                acc1[rr].z += pj1 * w1.z; acc1[rr].w += pj1 * w1.w;
            }
        }
    }
#pragma unroll
    for (int rr = 0; rr < 4; rr++) {
#pragma unroll
        for (int off = 16; off; off >>= 1) {
            ls0[rr] += __shfl_xor_sync(0xffffffffu, ls0[rr], off);
            ls1[rr] += __shfl_xor_sync(0xffffffffu, ls1[rr], off);
        }
    }
#pragma unroll
    for (int rr = 0; rr < 4; rr++) {
        int i = i0 + w * 4 + rr;
        float inv0 = 1.f / ls0[rr];
        float inv1 = 1.f / ls1[rr];
        float4 o0 = make_float4(eluf(acc0[rr].x * inv0), eluf(acc0[rr].y * inv0),
                                eluf(acc0[rr].z * inv0), eluf(acc0[rr].w * inv0));
        float4 o1 = make_float4(eluf(acc1[rr].x * inv1), eluf(acc1[rr].y * inv1),
                                eluf(acc1[rr].z * inv1), eluf(acc1[rr].w * inv1));
        *(float4*)&g_h[i][lane * 4] = o0;
        *(float4*)&g_h[i][NHID + lane * 4] = o1;
    }
}

// ---------------- K5: Wh2 = h @ W_out ----------------
__global__ void __launch_bounds__(256) k_gemm2(const float* __restrict__ Wout) {
    __shared__ float hs[4][256];
    __shared__ float ws[64][64];
    int tid = threadIdx.x;
    int i0 = blockIdx.x * 4;
    {
        int r = tid >> 6, c4 = (tid & 63) * 4;
        *(float4*)&hs[r][c4] = *(const float4*)&g_h[i0 + r][c4];
    }
    int r = tid >> 6, c = tid & 63;
    float acc = 0.f;
    for (int k0 = 0; k0 < 256; k0 += 64) {
        __syncthreads();
#pragma unroll
        for (int p = 0; p < 4; p++) {
            int idx = tid + p * 256;
            int kk = idx >> 4, cc = (idx & 15) * 4;
            *(float4*)&ws[kk][cc] = *(const float4*)&Wout[(size_t)(k0 + kk) * NCLS + cc];
        }
        __syncthreads();
#pragma unroll
        for (int kk = 0; kk < 64; kk++) acc += hs[r][k0 + kk] * ws[kk][c];
    }
    g_Wh2[i0 + r][c] = acc;
}

// ---------------- K6: layer-2 f1,f2 + max ----------------
__global__ void __launch_bounds__(256) k_fb(const float* __restrict__ a_out) {
    int tid = threadIdx.x, w = tid >> 5, lane = tid & 31;
    int row = blockIdx.x * 8 + w;
    float2 v  = *(const float2*)&g_Wh2[row][lane * 2];
    float2 as = *(const float2*)&a_out[lane * 2];
    float2 at = *(const float2*)&a_out[NCLS + lane * 2];
    float f1 = v.x * as.x + v.y * as.y;
    float f2 = v.x * at.x + v.y * at.y;
#pragma unroll
    for (int off = 16; off; off >>= 1) {
        f1 += __shfl_xor_sync(0xffffffffu, f1, off);
        f2 += __shfl_xor_sync(0xffffffffu, f2, off);
    }
    __shared__ float sm[8];
    if (lane == 0) { g_f1b[row] = f1; g_f2b[row] = f2; sm[w] = f2; }
    __syncthreads();
    if (tid == 0) {
        float m = sm[0];
#pragma unroll
        for (int k = 1; k < 8; k++) m = fmaxf(m, sm[k]);
        atomicMax(&g_max2, enc_f(m));
    }
}

// ---------------- K7: layer-2 fused masked attention -> mu ----------------
__global__ void __launch_bounds__(256) k_attn2(const int* __restrict__ adj,
                                               float* __restrict__ out_mu) {
    __shared__ float whS[32][64];   // 8 KB
    __shared__ int   adjS[32][32];  // 4 KB
    __shared__ float f2S[32];
    int tid = threadIdx.x, w = tid >> 5, lane = tid & 31;
    int i0 = blockIdx.x * 32;
    float F = dec_f(g_max2);
    float f1r[4], mh[4];
#pragma unroll
    for (int rr = 0; rr < 4; rr++) {
        int i = i0 + w * 4 + rr;
        f1r[rr] = g_f1b[i];
        mh[rr] = lrelu(f1r[rr] + F);
    }
    float2 acc[4]; float ls[4];
#pragma unroll
    for (int rr = 0; rr < 4; rr++) { acc[rr] = make_float2(0.f, 0.f); ls[rr] = 0.f; }

    for (int j0 = 0; j0 < Nn; j0 += 32) {
        __syncthreads();
        {
            const float4* src = (const float4*)&g_Wh2[j0][0];
            float4* dst = (float4*)&whS[0][0];
            dst[tid] = src[tid];
            dst[tid + 256] = src[tid + 256];
            int r = tid >> 3, c = (tid & 7) * 4;
            *(int4*)&adjS[r][c] = *(const int4*)&adj[(size_t)(i0 + r) * Nn + j0 + c];
            if (tid < 32) f2S[tid] = g_f2b[j0 + tid];
        }
        __syncthreads();
        float p[4];
#pragma unroll
        for (int rr = 0; rr < 4; rr++) {
            int m = adjS[w * 4 + rr][lane];
            float s = lrelu(f1r[rr] + f2S[lane]);
            p[rr] = m ? __expf(s - mh[rr]) : 0.f;
            ls[rr] += p[rr];
        }
#pragma unroll 8
        for (int jj = 0; jj < 32; jj++) {
            float2 wv = *(float2*)&whS[jj][lane * 2];
#pragma unroll
            for (int rr = 0; rr < 4; rr++) {
                float pj = __shfl_sync(0xffffffffu, p[rr], jj);
                acc[rr].x += pj * wv.x;
                acc[rr].y += pj * wv.y;
            }
        }
    }
#pragma unroll
    for (int rr = 0; rr < 4; rr++) {
#pragma unroll
        for (int off = 16; off; off >>= 1)
            ls[rr] += __shfl_xor_sync(0xffffffffu, ls[rr], off);
    }
#pragma unroll
    for (int rr = 0; rr < 4; rr++) {
        int i = i0 + w * 4 + rr;
        float inv = 1.f / ls[rr];
        float2 o = make_float2(eluf(acc[rr].x * inv), eluf(acc[rr].y * inv));
        *(float2*)&g_mu[i][lane * 2] = o;
        *(float2*)&out_mu[(size_t)i * NCLS + lane * 2] = o;
    }
}

// ---------------- K8: reconstruction = mu @ mu^T ----------------
__global__ void __launch_bounds__(256) k_recon(float* __restrict__ out) {
    __shared__ float As[64][68];   // [k][i], padded
    __shared__ float Bs[64][68];   // [k][j], padded
    int tid = threadIdx.x;
    int i0 = blockIdx.y * 64, j0 = blockIdx.x * 64;
#pragma unroll
    for (int p = 0; p < 4; p++) {
        int t = tid + p * 256;
        int r = t >> 4, q = (t & 15) * 4;
        float4 va = *(const float4*)&g_mu[i0 + r][q];
        As[q + 0][r] = va.x; As[q + 1][r] = va.y; As[q + 2][r] = va.z; As[q + 3][r] = va.w;
        float4 vb = *(const float4*)&g_mu[j0 + r][q];
        Bs[q + 0][r] = vb.x; Bs[q + 1][r] = vb.y; Bs[q + 2][r] = vb.z; Bs[q + 3][r] = vb.w;
    }
    __syncthreads();
    int tx = tid & 15, ty = tid >> 4;
    float acc[4][4] = {};
#pragma unroll 16
    for (int k = 0; k < 64; k++) {
        float4 a = *(float4*)&As[k][ty * 4];
        float4 b = *(float4*)&Bs[k][tx * 4];
        float av[4] = {a.x, a.y, a.z, a.w};
        float bv[4] = {b.x, b.y, b.z, b.w};
#pragma unroll
        for (int i = 0; i < 4; i++)
#pragma unroll
            for (int j = 0; j < 4; j++)
                acc[i][j] += av[i] * bv[j];
    }
#pragma unroll
    for (int i = 0; i < 4; i++) {
        float4 o = make_float4(acc[i][0], acc[i][1], acc[i][2], acc[i][3]);
        *(float4*)&out[(size_t)(i0 + ty * 4 + i) * Nn + j0 + tx * 4] = o;
    }
}

// ---------------- K9: class_pre = softmax(mu @ W1) ----------------
__global__ void __launch_bounds__(256) k_class(const float* __restrict__ W1,
                                               float* __restrict__ outc) {
    __shared__ float w1s[NCLS * CPRE];
    int tid = threadIdx.x, w = tid >> 5, lane = tid & 31;
    *(float4*)&w1s[tid * 4] = *(const float4*)&W1[tid * 4];
    __syncthreads();
    int row = blockIdx.x * 8 + w;
    int c = lane & 15, half = lane >> 4;
    float acc = 0.f;
#pragma unroll
    for (int k = 0; k < 32; k++) {
        int kk = half * 32 + k;
        acc += g_mu[row][kk] * w1s[kk * CPRE + c];
    }
    acc += __shfl_xor_sync(0xffffffffu, acc, 16);
    float m = acc;
#pragma unroll
    for (int off = 8; off; off >>= 1) m = fmaxf(m, __shfl_xor_sync(0xffffffffu, m, off));
    float e = __expf(acc - m);
    float s = e;
#pragma unroll
    for (int off = 8; off; off >>= 1) s += __shfl_xor_sync(0xffffffffu, s, off);
    if (lane < 16) outc[(size_t)row * CPRE + c] = e / s;
}

// ---------------- launch ----------------
extern "C" void kernel_launch(void* const* d_in, const int* in_sizes, int n_in,
                              void* d_out, int out_size) {
    const float* x       = (const float*)d_in[0];
    const int*   adj     = (const int*)d_in[1];
    const float* W_heads = (const float*)d_in[2];
    const float* a_heads = (const float*)d_in[3];
    const float* W_out   = (const float*)d_in[4];
    const float* a_out   = (const float*)d_in[5];
    const float* W1      = (const float*)d_in[6];
    float* out = (float*)d_out;
    float* out_recon = out;                                    // [N, N]
    float* out_mu    = out + (size_t)Nn * Nn;                  // [N, NCLS]
    float* out_class = out_mu + (size_t)Nn * NCLS;             // [N, CPRE]

    k_init<<<1, 1>>>();
    k_gemm1<<<dim3(Nn / 64, 4), 256>>>(x, W_heads);
    k_fheads<<<Nn / 8, 256>>>(a_heads);
    k_attn1<<<Nn / 32, 256>>>(adj);
    k_gemm2<<<Nn / 4, 256>>>(W_out);
    k_fb<<<Nn / 8, 256>>>(a_out);
    k_attn2<<<Nn / 32, 256>>>(adj, out_mu);
    k_recon<<<dim3(Nn / 64, Nn / 64), 256>>>(out_recon);
    k_class<<<Nn / 8, 256>>>(W1, out_class);
}

// round 2
// speedup vs baseline: 1.0003x; 1.0003x over previous
#include <cuda_runtime.h>

#define Nn   8192
#define FIN  512
#define NHID 128
#define NCLS 64
#define CPRE 16

// ---------------- scratch (static device globals; no allocation) ----------------
__device__ float    g_Wh1[Nn][2 * NHID];   // layer-1 Wh, both heads concat (8 MB)
__device__ float    g_f1h[2][Nn];
__device__ float    g_f2h[2][Nn];
__device__ unsigned g_max1[2];
__device__ float    g_h[Nn][2 * NHID];     // layer-1 output (8 MB)
__device__ float    g_Wh2[Nn][NCLS];       // 2 MB
__device__ float    g_f1b[Nn];
__device__ float    g_f2b[Nn];
__device__ unsigned g_max2;
__device__ float    g_mu[Nn][NCLS];        // 2 MB

// monotone float<->uint encoding for atomicMax on floats
__device__ __forceinline__ unsigned enc_f(float f) {
    unsigned u = __float_as_uint(f);
    return (u & 0x80000000u) ? ~u : (u | 0x80000000u);
}
__device__ __forceinline__ float dec_f(unsigned u) {
    return __uint_as_float((u & 0x80000000u) ? (u & 0x7fffffffu) : ~u);
}
__device__ __forceinline__ float lrelu(float x) { return x >= 0.f ? x : 0.2f * x; }
__device__ __forceinline__ float eluf(float x)  { return x > 0.f ? x : expm1f(x); }

__global__ void k_init() {
    g_max1[0] = 0u; g_max1[1] = 0u; g_max2 = 0u;
}

// ---------------- K1: Wh = x @ W  (both heads, output cols = h*128+c) ----------------
__global__ void __launch_bounds__(256) k_gemm1(const float* __restrict__ x,
                                               const float* __restrict__ W) {
    __shared__ float xs[16][64];   // [k][i]
    __shared__ float ws[16][64];   // [k][c]
    int i0 = blockIdx.x * 64;
    int c0 = blockIdx.y * 64;
    const float* Wp = W + (size_t)(c0 >> 7) * FIN * NHID;  // head base
    int cW = c0 & (NHID - 1);
    int tid = threadIdx.x;
    int tx = tid & 15, ty = tid >> 4;
    float acc[4][4] = {};
    for (int k0 = 0; k0 < FIN; k0 += 16) {
        {
            int r = tid >> 2, kk = (tid & 3) * 4;
            float4 v = *(const float4*)&x[(size_t)(i0 + r) * FIN + k0 + kk];
            xs[kk + 0][r] = v.x; xs[kk + 1][r] = v.y;
            xs[kk + 2][r] = v.z; xs[kk + 3][r] = v.w;
            int rk = tid >> 4, cc = (tid & 15) * 4;
            *(float4*)&ws[rk][cc] = *(const float4*)&Wp[(size_t)(k0 + rk) * NHID + cW + cc];
        }
        __syncthreads();
#pragma unroll
        for (int kk = 0; kk < 16; kk++) {
            float4 a = *(float4*)&xs[kk][ty * 4];
            float4 b = *(float4*)&ws[kk][tx * 4];
            float av[4] = {a.x, a.y, a.z, a.w};
            float bv[4] = {b.x, b.y, b.z, b.w};
#pragma unroll
            for (int i = 0; i < 4; i++)
#pragma unroll
                for (int j = 0; j < 4; j++)
                    acc[i][j] += av[i] * bv[j];
        }
        __syncthreads();
    }
#pragma unroll
    for (int i = 0; i < 4; i++) {
        float4 o = make_float4(acc[i][0], acc[i][1], acc[i][2], acc[i][3]);
        *(float4*)&g_Wh1[i0 + ty * 4 + i][c0 + tx * 4] = o;
    }
}

// ---------------- K2: per-row f1,f2 for both heads + global max(f2) ----------------
__global__ void __launch_bounds__(256) k_fheads(const float* __restrict__ a_heads) {
    int tid = threadIdx.x;
    int w = tid >> 5, lane = tid & 31;
    int row = blockIdx.x * 8 + w;
    float4 w0 = *(const float4*)&g_Wh1[row][lane * 4];
    float4 w1 = *(const float4*)&g_Wh1[row][NHID + lane * 4];
    float4 a0s = *(const float4*)&a_heads[lane * 4];
    float4 a0t = *(const float4*)&a_heads[NHID + lane * 4];
    float4 a1s = *(const float4*)&a_heads[2 * NHID + lane * 4];
    float4 a1t = *(const float4*)&a_heads[3 * NHID + lane * 4];
    float f10 = w0.x * a0s.x + w0.y * a0s.y + w0.z * a0s.z + w0.w * a0s.w;
    float f20 = w0.x * a0t.x + w0.y * a0t.y + w0.z * a0t.z + w0.w * a0t.w;
    float f11 = w1.x * a1s.x + w1.y * a1s.y + w1.z * a1s.z + w1.w * a1s.w;
    float f21 = w1.x * a1t.x + w1.y * a1t.y + w1.z * a1t.z + w1.w * a1t.w;
#pragma unroll
    for (int off = 16; off; off >>= 1) {
        f10 += __shfl_xor_sync(0xffffffffu, f10, off);
        f20 += __shfl_xor_sync(0xffffffffu, f20, off);
        f11 += __shfl_xor_sync(0xffffffffu, f11, off);
        f21 += __shfl_xor_sync(0xffffffffu, f21, off);
    }
    __shared__ float s0[8], s1[8];
    if (lane == 0) {
        g_f1h[0][row] = f10; g_f2h[0][row] = f20;
        g_f1h[1][row] = f11; g_f2h[1][row] = f21;
        s0[w] = f20; s1[w] = f21;
    }
    __syncthreads();
    if (tid == 0) {
        float m0 = s0[0], m1 = s1[0];
#pragma unroll
        for (int k = 1; k < 8; k++) { m0 = fmaxf(m0, s0[k]); m1 = fmaxf(m1, s1[k]); }
        atomicMax(&g_max1[0], enc_f(m0));
        atomicMax(&g_max1[1], enc_f(m1));
    }
}

// ---------------- K4: layer-1 fused masked attention, both heads ----------------
// 32 rows/CTA, 8 warps x 4 rows; streams j in tiles of 32; fixed-scale softmax.
__global__ void __launch_bounds__(256, 2) k_attn1(const int* __restrict__ adj) {
    __shared__ float whS[32][256];   // 32 KB
    __shared__ int   adjS[32][32];   // 4 KB
    __shared__ float f2S[2][32];
    int tid = threadIdx.x;
    int w = tid >> 5, lane = tid & 31;
    int i0 = blockIdx.x * 32;
    float F0 = dec_f(g_max1[0]), F1 = dec_f(g_max1[1]);
    float f10[4], f11[4], mh0[4], mh1[4];
#pragma unroll
    for (int rr = 0; rr < 4; rr++) {
        int i = i0 + w * 4 + rr;
        f10[rr] = g_f1h[0][i]; f11[rr] = g_f1h[1][i];
        mh0[rr] = lrelu(f10[rr] + F0);
        mh1[rr] = lrelu(f11[rr] + F1);
    }
    float4 acc0[4], acc1[4];
    float ls0[4], ls1[4];
#pragma unroll
    for (int rr = 0; rr < 4; rr++) {
        acc0[rr] = make_float4(0.f, 0.f, 0.f, 0.f);
        acc1[rr] = make_float4(0.f, 0.f, 0.f, 0.f);
        ls0[rr] = 0.f; ls1[rr] = 0.f;
    }

    for (int j0 = 0; j0 < Nn; j0 += 32) {
        __syncthreads();
        {
            const float4* src = (const float4*)&g_Wh1[j0][0];
            float4* dst = (float4*)&whS[0][0];
#pragma unroll
            for (int t = 0; t < 8; t++) dst[tid + t * 256] = src[tid + t * 256];
            int r = tid >> 3, c = (tid & 7) * 4;
            *(int4*)&adjS[r][c] = *(const int4*)&adj[(size_t)(i0 + r) * Nn + j0 + c];
            if (tid < 32) { f2S[0][tid] = g_f2h[0][j0 + tid]; f2S[1][tid] = g_f2h[1][j0 + tid]; }
        }
        __syncthreads();
        float p0[4], p1[4];
#pragma unroll
        for (int rr = 0; rr < 4; rr++) {
            int m = adjS[w * 4 + rr][lane];
            float s0 = lrelu(f10[rr] + f2S[0][lane]);
            float s1 = lrelu(f11[rr] + f2S[1][lane]);
            p0[rr] = m ? __expf(s0 - mh0[rr]) : 0.f;
            p1[rr] = m ? __expf(s1 - mh1[rr]) : 0.f;
            ls0[rr] += p0[rr]; ls1[rr] += p1[rr];
        }
#pragma unroll 8
        for (int jj = 0; jj < 32; jj++) {
            float4 w0 = *(float4*)&whS[jj][lane * 4];
            float4 w1 = *(float4*)&whS[jj][NHID + lane * 4];
#pragma unroll
            for (int rr = 0; rr < 4; rr++) {
                float pj0 = __shfl_sync(0xffffffffu, p0[rr], jj);
                float pj1 = __shfl_sync(0xffffffffu, p1[rr], jj);
                acc0[rr].x += pj0 * w0.x; acc0[rr].y += pj0 * w0.y;
                acc0[rr].z += pj0 * w0.z; acc0[rr].w += pj0 * w0.w;
                acc1[rr].x += pj1 * w1.x; acc1[rr].y += pj1 * w1.y;
                acc1[rr].z += pj1 * w1.z; acc1[rr].w += pj1 * w1.w;
            }
        }
    }
#pragma unroll
    for (int rr = 0; rr < 4; rr++) {
#pragma unroll
        for (int off = 16; off; off >>= 1) {
            ls0[rr] += __shfl_xor_sync(0xffffffffu, ls0[rr], off);
            ls1[rr] += __shfl_xor_sync(0xffffffffu, ls1[rr], off);
        }
    }
#pragma unroll
    for (int rr = 0; rr < 4; rr++) {
        int i = i0 + w * 4 + rr;
        float inv0 = 1.f / ls0[rr];
        float inv1 = 1.f / ls1[rr];
        float4 o0 = make_float4(eluf(acc0[rr].x * inv0), eluf(acc0[rr].y * inv0),
                                eluf(acc0[rr].z * inv0), eluf(acc0[rr].w * inv0));
        float4 o1 = make_float4(eluf(acc1[rr].x * inv1), eluf(acc1[rr].y * inv1),
                                eluf(acc1[rr].z * inv1), eluf(acc1[rr].w * inv1));
        *(float4*)&g_h[i][lane * 4] = o0;
        *(float4*)&g_h[i][NHID + lane * 4] = o1;
    }
}

// ---------------- K5: Wh2 = h @ W_out ----------------
__global__ void __launch_bounds__(256) k_gemm2(const float* __restrict__ Wout) {
    __shared__ float hs[4][256];
    __shared__ float ws[64][64];
    int tid = threadIdx.x;
    int i0 = blockIdx.x * 4;
    {
        int r = tid >> 6, c4 = (tid & 63) * 4;
        *(float4*)&hs[r][c4] = *(const float4*)&g_h[i0 + r][c4];
    }
    int r = tid >> 6, c = tid & 63;
    float acc = 0.f;
    for (int k0 = 0; k0 < 256; k0 += 64) {
        __syncthreads();
#pragma unroll
        for (int p = 0; p < 4; p++) {
            int idx = tid + p * 256;
            int kk = idx >> 4, cc = (idx & 15) * 4;
            *(float4*)&ws[kk][cc] = *(const float4*)&Wout[(size_t)(k0 + kk) * NCLS + cc];
        }
        __syncthreads();
#pragma unroll
        for (int kk = 0; kk < 64; kk++) acc += hs[r][k0 + kk] * ws[kk][c];
    }
    g_Wh2[i0 + r][c] = acc;
}

// ---------------- K6: layer-2 f1,f2 + max ----------------
__global__ void __launch_bounds__(256) k_fb(const float* __restrict__ a_out) {
    int tid = threadIdx.x, w = tid >> 5, lane = tid & 31;
    int row = blockIdx.x * 8 + w;
    float2 v  = *(const float2*)&g_Wh2[row][lane * 2];
    float2 as = *(const float2*)&a_out[lane * 2];
    float2 at = *(const float2*)&a_out[NCLS + lane * 2];
    float f1 = v.x * as.x + v.y * as.y;
    float f2 = v.x * at.x + v.y * at.y;
#pragma unroll
    for (int off = 16; off; off >>= 1) {
        f1 += __shfl_xor_sync(0xffffffffu, f1, off);
        f2 += __shfl_xor_sync(0xffffffffu, f2, off);
    }
    __shared__ float sm[8];
    if (lane == 0) { g_f1b[row] = f1; g_f2b[row] = f2; sm[w] = f2; }
    __syncthreads();
    if (tid == 0) {
        float m = sm[0];
#pragma unroll
        for (int k = 1; k < 8; k++) m = fmaxf(m, sm[k]);
        atomicMax(&g_max2, enc_f(m));
    }
}

// ---------------- K7: layer-2 fused masked attention -> mu ----------------
__global__ void __launch_bounds__(256) k_attn2(const int* __restrict__ adj,
                                               float* __restrict__ out_mu) {
    __shared__ float whS[32][64];   // 8 KB
    __shared__ int   adjS[32][32];  // 4 KB
    __shared__ float f2S[32];
    int tid = threadIdx.x, w = tid >> 5, lane = tid & 31;
    int i0 = blockIdx.x * 32;
    float F = dec_f(g_max2);
    float f1r[4], mh[4];
#pragma unroll
    for (int rr = 0; rr < 4; rr++) {
        int i = i0 + w * 4 + rr;
        f1r[rr] = g_f1b[i];
        mh[rr] = lrelu(f1r[rr] + F);
    }
    float2 acc[4]; float ls[4];
#pragma unroll
    for (int rr = 0; rr < 4; rr++) { acc[rr] = make_float2(0.f, 0.f); ls[rr] = 0.f; }

    for (int j0 = 0; j0 < Nn; j0 += 32) {
        __syncthreads();
        {
            const float4* src = (const float4*)&g_Wh2[j0][0];
            float4* dst = (float4*)&whS[0][0];
            dst[tid] = src[tid];
            dst[tid + 256] = src[tid + 256];
            int r = tid >> 3, c = (tid & 7) * 4;
            *(int4*)&adjS[r][c] = *(const int4*)&adj[(size_t)(i0 + r) * Nn + j0 + c];
            if (tid < 32) f2S[tid] = g_f2b[j0 + tid];
        }
        __syncthreads();
        float p[4];
#pragma unroll
        for (int rr = 0; rr < 4; rr++) {
            int m = adjS[w * 4 + rr][lane];
            float s = lrelu(f1r[rr] + f2S[lane]);
            p[rr] = m ? __expf(s - mh[rr]) : 0.f;
            ls[rr] += p[rr];
        }
#pragma unroll 8
        for (int jj = 0; jj < 32; jj++) {
            float2 wv = *(float2*)&whS[jj][lane * 2];
#pragma unroll
            for (int rr = 0; rr < 4; rr++) {
                float pj = __shfl_sync(0xffffffffu, p[rr], jj);
                acc[rr].x += pj * wv.x;
                acc[rr].y += pj * wv.y;
            }
        }
    }
#pragma unroll
    for (int rr = 0; rr < 4; rr++) {
#pragma unroll
        for (int off = 16; off; off >>= 1)
            ls[rr] += __shfl_xor_sync(0xffffffffu, ls[rr], off);
    }
#pragma unroll
    for (int rr = 0; rr < 4; rr++) {
        int i = i0 + w * 4 + rr;
        float inv = 1.f / ls[rr];
        float2 o = make_float2(eluf(acc[rr].x * inv), eluf(acc[rr].y * inv));
        *(float2*)&g_mu[i][lane * 2] = o;
        *(float2*)&out_mu[(size_t)i * NCLS + lane * 2] = o;
    }
}

// ---------------- K8: reconstruction = mu @ mu^T ----------------
__global__ void __launch_bounds__(256) k_recon(float* __restrict__ out) {
    __shared__ float As[64][68];   // [k][i], padded
    __shared__ float Bs[64][68];   // [k][j], padded
    int tid = threadIdx.x;
    int i0 = blockIdx.y * 64, j0 = blockIdx.x * 64;
#pragma unroll
    for (int p = 0; p < 4; p++) {
        int t = tid + p * 256;
        int r = t >> 4, q = (t & 15) * 4;
        float4 va = *(const float4*)&g_mu[i0 + r][q];
        As[q + 0][r] = va.x; As[q + 1][r] = va.y; As[q + 2][r] = va.z; As[q + 3][r] = va.w;
        float4 vb = *(const float4*)&g_mu[j0 + r][q];
        Bs[q + 0][r] = vb.x; Bs[q + 1][r] = vb.y; Bs[q + 2][r] = vb.z; Bs[q + 3][r] = vb.w;
    }
    __syncthreads();
    int tx = tid & 15, ty = tid >> 4;
    float acc[4][4] = {};
#pragma unroll 16
    for (int k = 0; k < 64; k++) {
        float4 a = *(float4*)&As[k][ty * 4];
        float4 b = *(float4*)&Bs[k][tx * 4];
        float av[4] = {a.x, a.y, a.z, a.w};
        float bv[4] = {b.x, b.y, b.z, b.w};
#pragma unroll
        for (int i = 0; i < 4; i++)
#pragma unroll
            for (int j = 0; j < 4; j++)
                acc[i][j] += av[i] * bv[j];
    }
#pragma unroll
    for (int i = 0; i < 4; i++) {
        float4 o = make_float4(acc[i][0], acc[i][1], acc[i][2], acc[i][3]);
        *(float4*)&out[(size_t)(i0 + ty * 4 + i) * Nn + j0 + tx * 4] = o;
    }
}

// ---------------- K9: class_pre = softmax(mu @ W1) ----------------
__global__ void __launch_bounds__(256) k_class(const float* __restrict__ W1,
                                               float* __restrict__ outc) {
    __shared__ float w1s[NCLS * CPRE];
    int tid = threadIdx.x, w = tid >> 5, lane = tid & 31;
    *(float4*)&w1s[tid * 4] = *(const float4*)&W1[tid * 4];
    __syncthreads();
    int row = blockIdx.x * 8 + w;
    int c = lane & 15, half = lane >> 4;
    float acc = 0.f;
#pragma unroll
    for (int k = 0; k < 32; k++) {
        int kk = half * 32 + k;
        acc += g_mu[row][kk] * w1s[kk * CPRE + c];
    }
    acc += __shfl_xor_sync(0xffffffffu, acc, 16);
    float m = acc;
#pragma unroll
    for (int off = 8; off; off >>= 1) m = fmaxf(m, __shfl_xor_sync(0xffffffffu, m, off));
    float e = __expf(acc - m);
    float s = e;
#pragma unroll
    for (int off = 8; off; off >>= 1) s += __shfl_xor_sync(0xffffffffu, s, off);
    if (lane < 16) outc[(size_t)row * CPRE + c] = e / s;
}

// ---------------- launch ----------------
extern "C" void kernel_launch(void* const* d_in, const int* in_sizes, int n_in,
                              void* d_out, int out_size) {
    const float* x       = (const float*)d_in[0];
    const int*   adj     = (const int*)d_in[1];
    const float* W_heads = (const float*)d_in[2];
    const float* a_heads = (const float*)d_in[3];
    const float* W_out   = (const float*)d_in[4];
    const float* a_out   = (const float*)d_in[5];
    const float* W1      = (const float*)d_in[6];
    float* out = (float*)d_out;
    float* out_recon = out;                                    // [N, N]
    float* out_mu    = out + (size_t)Nn * Nn;                  // [N, NCLS]
    float* out_class = out_mu + (size_t)Nn * NCLS;             // [N, CPRE]

    k_init<<<1, 1>>>();
    k_gemm1<<<dim3(Nn / 64, 4), 256>>>(x, W_heads);
    k_fheads<<<Nn / 8, 256>>>(a_heads);
    k_attn1<<<Nn / 32, 256>>>(adj);
    k_gemm2<<<Nn / 4, 256>>>(W_out);
    k_fb<<<Nn / 8, 256>>>(a_out);
    k_attn2<<<Nn / 32, 256>>>(adj, out_mu);
    k_recon<<<dim3(Nn / 64, Nn / 64), 256>>>(out_recon);
    k_class<<<Nn / 8, 256>>>(W1, out_class);
}